// round 13
// baseline (speedup 1.0000x reference)
#include <cuda_runtime.h>
#include <math_constants.h>

#define BATCH 131072
#define NUM_CLASSES 1000
#define C4 250                 // float4 chunks per row (1000 floats)
#define MAIN_BLOCK 256
#define WARPS_PER_BLOCK (MAIN_BLOCK / 32)
#define GRID_BLOCKS 2048                         // 16384 warps
#define TOTAL_WARPS (GRID_BLOCKS * WARPS_PER_BLOCK)
#define ROWS_PER_WARP (BATCH / TOTAL_WARPS)      // 8, exact

// Zero-initialized at module load. The finalize kernel re-zeros after use, so
// every graph replay starts from the same (zeroed) state.
__device__ int g_counts[NUM_CLASSES];
__device__ int g_hits[NUM_CLASSES];

// ---------------------------------------------------------------------------
// Kernel 1: persistent warps — each warp handles 8 rows (grid-stride).
// Per row: dual argmax (pred & true), first-index tie-break, histogram
// atomics. Loads for the next row overlap the reduce of the current one.
// ---------------------------------------------------------------------------
__global__ void __launch_bounds__(MAIN_BLOCK)
argmax_hist_kernel(const float4* __restrict__ y_pred,
                   const float4* __restrict__ y_true) {
    const int warp_gid = (blockIdx.x * WARPS_PER_BLOCK) + (threadIdx.x >> 5);
    const int lane     = threadIdx.x & 31;

    for (int r = 0; r < ROWS_PER_WARP; r++) {
        const int row = warp_gid + r * TOTAL_WARPS;   // coalesced across warps
        const float4* __restrict__ rp = y_pred + (size_t)row * C4;
        const float4* __restrict__ rt = y_true + (size_t)row * C4;

        // Unpredicated loads: clamp index to 249. Duplicated chunk-249 reads
        // are harmless for argmax (strict '>' keeps the first occurrence;
        // cross-lane ties resolve by smaller index in the warp reduce).
        // 16 independent LDG.128 per lane; __ldcs = evict-first.
        float4 a[8], b[8];
        int idx[8];
        #pragma unroll
        for (int k = 0; k < 8; k++) {
            const int i = min(k * 32 + lane, C4 - 1);
            idx[k] = i * 4;
            a[k] = __ldcs(rp + i);
            b[k] = __ldcs(rt + i);
        }

        float pbest = -CUDART_INF_F; int pidx = 0;
        float tbest = -CUDART_INF_F; int tidx = 0;
        #pragma unroll
        for (int k = 0; k < 8; k++) {
            const int base = idx[k];
            if (a[k].x > pbest) { pbest = a[k].x; pidx = base + 0; }
            if (a[k].y > pbest) { pbest = a[k].y; pidx = base + 1; }
            if (a[k].z > pbest) { pbest = a[k].z; pidx = base + 2; }
            if (a[k].w > pbest) { pbest = a[k].w; pidx = base + 3; }
            if (b[k].x > tbest) { tbest = b[k].x; tidx = base + 0; }
            if (b[k].y > tbest) { tbest = b[k].y; tidx = base + 1; }
            if (b[k].z > tbest) { tbest = b[k].z; tidx = base + 2; }
            if (b[k].w > tbest) { tbest = b[k].w; tidx = base + 3; }
        }

        // Warp argmax reduce; tie-break toward smaller index.
        #pragma unroll
        for (int off = 16; off > 0; off >>= 1) {
            float pv = __shfl_down_sync(0xFFFFFFFFu, pbest, off);
            int   pi = __shfl_down_sync(0xFFFFFFFFu, pidx,  off);
            if (pv > pbest || (pv == pbest && pi < pidx)) { pbest = pv; pidx = pi; }
            float tv = __shfl_down_sync(0xFFFFFFFFu, tbest, off);
            int   ti = __shfl_down_sync(0xFFFFFFFFu, tidx,  off);
            if (tv > tbest || (tv == tbest && ti < tidx)) { tbest = tv; tidx = ti; }
        }

        if (lane == 0) {
            atomicAdd(&g_counts[tidx], 1);
            if (pidx == tidx) atomicAdd(&g_hits[tidx], 1);
        }
    }
}

// ---------------------------------------------------------------------------
// Kernel 2 (PDL secondary): 1024 threads, one class per thread, fast
// division. Gates on the primary's completion, computes -mean_recall, then
// resets histograms for the next graph replay.
// ---------------------------------------------------------------------------
__global__ void __launch_bounds__(1024)
finalize_kernel(float* __restrict__ out) {
    cudaGridDependencySynchronize();

    const int tid = threadIdx.x;

    float rec = 0.0f, prs = 0.0f;
    if (tid < NUM_CLASSES) {
        const int cnt = g_counts[tid];
        if (cnt > 0) {
            prs = 1.0f;
            // MUFU rcp + mul; rel-err ~2^-22, far below the 1e-3 tolerance.
            rec = __fdividef((float)g_hits[tid], (float)cnt);
        }
    }

    // 32-warp reduction: warp shuffle, then one warp over smem.
    __shared__ float s_rec[32];
    __shared__ float s_prs[32];
    #pragma unroll
    for (int off = 16; off > 0; off >>= 1) {
        rec += __shfl_down_sync(0xFFFFFFFFu, rec, off);
        prs += __shfl_down_sync(0xFFFFFFFFu, prs, off);
    }
    const int warp = tid >> 5;
    const int lane = tid & 31;
    if (lane == 0) { s_rec[warp] = rec; s_prs[warp] = prs; }
    __syncthreads();
    if (warp == 0) {
        rec = s_rec[lane];
        prs = s_prs[lane];
        #pragma unroll
        for (int off = 16; off > 0; off >>= 1) {
            rec += __shfl_down_sync(0xFFFFFFFFu, rec, off);
            prs += __shfl_down_sync(0xFFFFFFFFu, prs, off);
        }
        if (lane == 0)
            out[0] = (prs > 0.0f) ? -__fdividef(rec, prs) : 0.0f;
    }

    // Reset for the next replay (reads above are ordered before these writes
    // by the __syncthreads in the reduction path).
    if (tid < NUM_CLASSES) {
        g_counts[tid] = 0;
        g_hits[tid]   = 0;
    }
}

// ---------------------------------------------------------------------------
extern "C" void kernel_launch(void* const* d_in, const int* in_sizes, int n_in,
                              void* d_out, int out_size) {
    const float4* y_pred = (const float4*)d_in[0];
    const float4* y_true = (const float4*)d_in[1];
    float* out = (float*)d_out;

    argmax_hist_kernel<<<GRID_BLOCKS, MAIN_BLOCK>>>(y_pred, y_true);

    // PDL launch of the finalize kernel: overlap its launch ramp with the
    // primary kernel's execution (R9 best config — no explicit trigger).
    cudaLaunchConfig_t cfg = {};
    cfg.gridDim  = dim3(1, 1, 1);
    cfg.blockDim = dim3(1024, 1, 1);
    cfg.dynamicSmemBytes = 0;
    cudaLaunchAttribute attrs[1];
    attrs[0].id = cudaLaunchAttributeProgrammaticStreamSerialization;
    attrs[0].val.programmaticStreamSerializationAllowed = 1;
    cfg.attrs = attrs;
    cfg.numAttrs = 1;
    cudaLaunchKernelEx(&cfg, finalize_kernel, out);
}

// round 14
// speedup vs baseline: 1.0343x; 1.0343x over previous
#include <cuda_runtime.h>
#include <math_constants.h>

#define BATCH 131072
#define NUM_CLASSES 1000
#define C4 250                 // float4 chunks per row (1000 floats)
#define MAIN_BLOCK 512
#define WARPS_PER_BLOCK (MAIN_BLOCK / 32)
#define GRID_BLOCKS (BATCH / WARPS_PER_BLOCK)   // 8192, exact

// Zero-initialized at module load. The finalize kernel re-zeros after use, so
// every graph replay starts from the same (zeroed) state.
__device__ int g_counts[NUM_CLASSES];
__device__ int g_hits[NUM_CLASSES];

// ---------------------------------------------------------------------------
// Kernel 1: one warp per row (R9 structure — measured best at 91.6% of HBM
// spec). Dual argmax (pred & true), first-index tie-break, histogram atomics.
// Monolithic body: fresh CTAs keep the L1tex queue full while other warps sit
// in their reduce/atomic tails.
// ---------------------------------------------------------------------------
__global__ void __launch_bounds__(MAIN_BLOCK)
argmax_hist_kernel(const float4* __restrict__ y_pred,
                   const float4* __restrict__ y_true) {
    const int warp_id = (blockIdx.x * WARPS_PER_BLOCK) + (threadIdx.x >> 5);
    const int lane    = threadIdx.x & 31;

    const float4* __restrict__ rp = y_pred + (size_t)warp_id * C4;
    const float4* __restrict__ rt = y_true + (size_t)warp_id * C4;

    // Unpredicated loads: clamp index to 249. Duplicated chunk-249 reads are
    // harmless for argmax (strict '>' keeps the first occurrence; cross-lane
    // ties resolve by smaller index in the warp reduce) and coalesce to the
    // same sector. 16 independent LDG.128 per lane; __ldcs = evict-first.
    float4 a[8], b[8];
    int idx[8];
    #pragma unroll
    for (int k = 0; k < 8; k++) {
        const int i = min(k * 32 + lane, C4 - 1);
        idx[k] = i * 4;
        a[k] = __ldcs(rp + i);
        b[k] = __ldcs(rt + i);
    }

    float pbest = -CUDART_INF_F; int pidx = 0;
    float tbest = -CUDART_INF_F; int tidx = 0;
    #pragma unroll
    for (int k = 0; k < 8; k++) {
        const int base = idx[k];
        if (a[k].x > pbest) { pbest = a[k].x; pidx = base + 0; }
        if (a[k].y > pbest) { pbest = a[k].y; pidx = base + 1; }
        if (a[k].z > pbest) { pbest = a[k].z; pidx = base + 2; }
        if (a[k].w > pbest) { pbest = a[k].w; pidx = base + 3; }
        if (b[k].x > tbest) { tbest = b[k].x; tidx = base + 0; }
        if (b[k].y > tbest) { tbest = b[k].y; tidx = base + 1; }
        if (b[k].z > tbest) { tbest = b[k].z; tidx = base + 2; }
        if (b[k].w > tbest) { tbest = b[k].w; tidx = base + 3; }
    }

    // Warp argmax reduce; tie-break toward smaller index (first occurrence).
    #pragma unroll
    for (int off = 16; off > 0; off >>= 1) {
        float pv = __shfl_down_sync(0xFFFFFFFFu, pbest, off);
        int   pi = __shfl_down_sync(0xFFFFFFFFu, pidx,  off);
        if (pv > pbest || (pv == pbest && pi < pidx)) { pbest = pv; pidx = pi; }
        float tv = __shfl_down_sync(0xFFFFFFFFu, tbest, off);
        int   ti = __shfl_down_sync(0xFFFFFFFFu, tidx,  off);
        if (tv > tbest || (tv == tbest && ti < tidx)) { tbest = tv; tidx = ti; }
    }

    if (lane == 0) {
        atomicAdd(&g_counts[tidx], 1);
        if (pidx == tidx) atomicAdd(&g_hits[tidx], 1);
    }
}

// ---------------------------------------------------------------------------
// Kernel 2 (PDL secondary): 1024 threads, one class per thread, fast
// division. Gates on the primary's completion, computes -mean_recall, then
// resets histograms for the next graph replay.
// ---------------------------------------------------------------------------
__global__ void __launch_bounds__(1024)
finalize_kernel(float* __restrict__ out) {
    cudaGridDependencySynchronize();

    const int tid = threadIdx.x;

    float rec = 0.0f, prs = 0.0f;
    if (tid < NUM_CLASSES) {
        const int cnt = g_counts[tid];
        if (cnt > 0) {
            prs = 1.0f;
            // MUFU rcp + mul; rel-err ~2^-22, far below the 1e-3 tolerance.
            rec = __fdividef((float)g_hits[tid], (float)cnt);
        }
    }

    // 32-warp reduction: warp shuffle, then one warp over smem.
    __shared__ float s_rec[32];
    __shared__ float s_prs[32];
    #pragma unroll
    for (int off = 16; off > 0; off >>= 1) {
        rec += __shfl_down_sync(0xFFFFFFFFu, rec, off);
        prs += __shfl_down_sync(0xFFFFFFFFu, prs, off);
    }
    const int warp = tid >> 5;
    const int lane = tid & 31;
    if (lane == 0) { s_rec[warp] = rec; s_prs[warp] = prs; }
    __syncthreads();
    if (warp == 0) {
        rec = s_rec[lane];
        prs = s_prs[lane];
        #pragma unroll
        for (int off = 16; off > 0; off >>= 1) {
            rec += __shfl_down_sync(0xFFFFFFFFu, rec, off);
            prs += __shfl_down_sync(0xFFFFFFFFu, prs, off);
        }
        if (lane == 0)
            out[0] = (prs > 0.0f) ? -__fdividef(rec, prs) : 0.0f;
    }

    // Reset for the next replay (reads above are ordered before these writes
    // by the __syncthreads in the reduction path).
    if (tid < NUM_CLASSES) {
        g_counts[tid] = 0;
        g_hits[tid]   = 0;
    }
}

// ---------------------------------------------------------------------------
extern "C" void kernel_launch(void* const* d_in, const int* in_sizes, int n_in,
                              void* d_out, int out_size) {
    const float4* y_pred = (const float4*)d_in[0];
    const float4* y_true = (const float4*)d_in[1];
    float* out = (float*)d_out;

    argmax_hist_kernel<<<GRID_BLOCKS, MAIN_BLOCK>>>(y_pred, y_true);

    // PDL launch of the finalize kernel: overlap its launch ramp with the
    // primary kernel's execution (R9 best config — no explicit trigger).
    cudaLaunchConfig_t cfg = {};
    cfg.gridDim  = dim3(1, 1, 1);
    cfg.blockDim = dim3(1024, 1, 1);
    cfg.dynamicSmemBytes = 0;
    cudaLaunchAttribute attrs[1];
    attrs[0].id = cudaLaunchAttributeProgrammaticStreamSerialization;
    attrs[0].val.programmaticStreamSerializationAllowed = 1;
    cfg.attrs = attrs;
    cfg.numAttrs = 1;
    cudaLaunchKernelEx(&cfg, finalize_kernel, out);
}

// round 15
// speedup vs baseline: 1.0480x; 1.0132x over previous
#include <cuda_runtime.h>
#include <math_constants.h>

#define BATCH 131072
#define NUM_CLASSES 1000
#define C4 250                 // float4 chunks per row (1000 floats)
#define MAIN_BLOCK 256
#define WARPS_PER_BLOCK (MAIN_BLOCK / 32)
#define GRID_BLOCKS (BATCH / WARPS_PER_BLOCK)   // 16384, exact

// Packed per-class histogram: low 32 bits = count, high 32 bits = hits.
// Zero-initialized at module load; finalize re-zeros after use so every
// graph replay starts from the same state. Max count 131072 per class —
// no carry into the high word possible.
__device__ unsigned long long g_hist[NUM_CLASSES];

// ---------------------------------------------------------------------------
// Kernel 1: one warp per row (R9 geometry — measured best, 7.3 TB/s).
// Dual argmax (pred & true), first-index tie-break, ONE packed 64-bit
// histogram atomic per row.
// ---------------------------------------------------------------------------
__global__ void __launch_bounds__(MAIN_BLOCK)
argmax_hist_kernel(const float4* __restrict__ y_pred,
                   const float4* __restrict__ y_true) {
    const int warp_id = (blockIdx.x * WARPS_PER_BLOCK) + (threadIdx.x >> 5);
    const int lane    = threadIdx.x & 31;

    const float4* __restrict__ rp = y_pred + (size_t)warp_id * C4;
    const float4* __restrict__ rt = y_true + (size_t)warp_id * C4;

    // Unpredicated loads: clamp index to 249. Duplicated chunk-249 reads are
    // harmless for argmax (strict '>' keeps the first occurrence; cross-lane
    // ties resolve by smaller index in the warp reduce) and coalesce to the
    // same sector. 16 independent LDG.128 per lane; __ldcs = evict-first.
    float4 a[8], b[8];
    int idx[8];
    #pragma unroll
    for (int k = 0; k < 8; k++) {
        const int i = min(k * 32 + lane, C4 - 1);
        idx[k] = i * 4;
        a[k] = __ldcs(rp + i);
        b[k] = __ldcs(rt + i);
    }

    float pbest = -CUDART_INF_F; int pidx = 0;
    float tbest = -CUDART_INF_F; int tidx = 0;
    #pragma unroll
    for (int k = 0; k < 8; k++) {
        const int base = idx[k];
        if (a[k].x > pbest) { pbest = a[k].x; pidx = base + 0; }
        if (a[k].y > pbest) { pbest = a[k].y; pidx = base + 1; }
        if (a[k].z > pbest) { pbest = a[k].z; pidx = base + 2; }
        if (a[k].w > pbest) { pbest = a[k].w; pidx = base + 3; }
        if (b[k].x > tbest) { tbest = b[k].x; tidx = base + 0; }
        if (b[k].y > tbest) { tbest = b[k].y; tidx = base + 1; }
        if (b[k].z > tbest) { tbest = b[k].z; tidx = base + 2; }
        if (b[k].w > tbest) { tbest = b[k].w; tidx = base + 3; }
    }

    // Warp argmax reduce; tie-break toward smaller index (first occurrence).
    #pragma unroll
    for (int off = 16; off > 0; off >>= 1) {
        float pv = __shfl_down_sync(0xFFFFFFFFu, pbest, off);
        int   pi = __shfl_down_sync(0xFFFFFFFFu, pidx,  off);
        if (pv > pbest || (pv == pbest && pi < pidx)) { pbest = pv; pidx = pi; }
        float tv = __shfl_down_sync(0xFFFFFFFFu, tbest, off);
        int   ti = __shfl_down_sync(0xFFFFFFFFu, tidx,  off);
        if (tv > tbest || (tv == tbest && ti < tidx)) { tbest = tv; tidx = ti; }
    }

    if (lane == 0) {
        // count += 1; hit += (pred == true) — one L2 atomic instead of two.
        const unsigned long long v =
            1ull | ((unsigned long long)(pidx == tidx) << 32);
        atomicAdd(&g_hist[tidx], v);
    }
}

// ---------------------------------------------------------------------------
// Kernel 2 (PDL secondary): 1024 threads, one class per thread, fast
// division. Gates on the primary's completion, computes -mean_recall, then
// resets the histogram for the next graph replay.
// ---------------------------------------------------------------------------
__global__ void __launch_bounds__(1024)
finalize_kernel(float* __restrict__ out) {
    cudaGridDependencySynchronize();

    const int tid = threadIdx.x;

    float rec = 0.0f, prs = 0.0f;
    if (tid < NUM_CLASSES) {
        const unsigned long long v = g_hist[tid];
        const unsigned int cnt  = (unsigned int)v;
        const unsigned int hits = (unsigned int)(v >> 32);
        if (cnt > 0) {
            prs = 1.0f;
            // MUFU rcp + mul; rel-err ~2^-22, far below the 1e-3 tolerance.
            rec = __fdividef((float)hits, (float)cnt);
        }
    }

    // 32-warp reduction: warp shuffle, then one warp over smem.
    __shared__ float s_rec[32];
    __shared__ float s_prs[32];
    #pragma unroll
    for (int off = 16; off > 0; off >>= 1) {
        rec += __shfl_down_sync(0xFFFFFFFFu, rec, off);
        prs += __shfl_down_sync(0xFFFFFFFFu, prs, off);
    }
    const int warp = tid >> 5;
    const int lane = tid & 31;
    if (lane == 0) { s_rec[warp] = rec; s_prs[warp] = prs; }
    __syncthreads();
    if (warp == 0) {
        rec = s_rec[lane];
        prs = s_prs[lane];
        #pragma unroll
        for (int off = 16; off > 0; off >>= 1) {
            rec += __shfl_down_sync(0xFFFFFFFFu, rec, off);
            prs += __shfl_down_sync(0xFFFFFFFFu, prs, off);
        }
        if (lane == 0)
            out[0] = (prs > 0.0f) ? -__fdividef(rec, prs) : 0.0f;
    }

    // Reset for the next replay (reads above are ordered before these writes
    // by the __syncthreads in the reduction path).
    if (tid < NUM_CLASSES) {
        g_hist[tid] = 0ull;
    }
}

// ---------------------------------------------------------------------------
extern "C" void kernel_launch(void* const* d_in, const int* in_sizes, int n_in,
                              void* d_out, int out_size) {
    const float4* y_pred = (const float4*)d_in[0];
    const float4* y_true = (const float4*)d_in[1];
    float* out = (float*)d_out;

    argmax_hist_kernel<<<GRID_BLOCKS, MAIN_BLOCK>>>(y_pred, y_true);

    // PDL launch of the finalize kernel: overlap its launch ramp with the
    // primary kernel's execution (R9 best config — no explicit trigger).
    cudaLaunchConfig_t cfg = {};
    cfg.gridDim  = dim3(1, 1, 1);
    cfg.blockDim = dim3(1024, 1, 1);
    cfg.dynamicSmemBytes = 0;
    cudaLaunchAttribute attrs[1];
    attrs[0].id = cudaLaunchAttributeProgrammaticStreamSerialization;
    attrs[0].val.programmaticStreamSerializationAllowed = 1;
    cfg.attrs = attrs;
    cfg.numAttrs = 1;
    cudaLaunchKernelEx(&cfg, finalize_kernel, out);
}

// round 16
// speedup vs baseline: 1.0653x; 1.0165x over previous
#include <cuda_runtime.h>
#include <math_constants.h>

#define BATCH 131072
#define NUM_CLASSES 1000
#define C4 250                 // float4 chunks per row (1000 floats)
#define MAIN_BLOCK 256
#define WARPS_PER_BLOCK (MAIN_BLOCK / 32)
#define GRID_BLOCKS (BATCH / WARPS_PER_BLOCK)   // 16384, exact

// Packed per-class histogram: low 32 bits = count, high 32 bits = hits.
// Zero-initialized at module load; finalize re-zeros after use so every
// graph replay starts from the same state. Max count 131072 per class —
// no carry into the high word possible.
__device__ unsigned long long g_hist[NUM_CLASSES];

// Order-preserving fp32 -> u32 map (total order, max-compatible).
__device__ __forceinline__ unsigned int f32_ordered_key(float v) {
    unsigned int b = __float_as_uint(v);
    return (b & 0x80000000u) ? ~b : (b | 0x80000000u);
}

// ---------------------------------------------------------------------------
// Kernel 1: one warp per row (R9 geometry — measured best, 7.3 TB/s).
// Dual argmax via hardware REDUX.SYNC (max of ordered key, then min-index
// tie-break = first occurrence), ONE packed 64-bit histogram atomic per row.
// ---------------------------------------------------------------------------
__global__ void __launch_bounds__(MAIN_BLOCK)
argmax_hist_kernel(const float4* __restrict__ y_pred,
                   const float4* __restrict__ y_true) {
    const int warp_id = (blockIdx.x * WARPS_PER_BLOCK) + (threadIdx.x >> 5);
    const int lane    = threadIdx.x & 31;

    const float4* __restrict__ rp = y_pred + (size_t)warp_id * C4;
    const float4* __restrict__ rt = y_true + (size_t)warp_id * C4;

    // Unpredicated loads: clamp index to 249. Duplicated chunk-249 reads are
    // harmless for argmax (strict '>' keeps the first occurrence; cross-lane
    // ties resolve to the smallest index by the redux-min below) and coalesce
    // to the same sector. 16 independent LDG.128 per lane; __ldcs=evict-first.
    float4 a[8], b[8];
    int idx[8];
    #pragma unroll
    for (int k = 0; k < 8; k++) {
        const int i = min(k * 32 + lane, C4 - 1);
        idx[k] = i * 4;
        a[k] = __ldcs(rp + i);
        b[k] = __ldcs(rt + i);
    }

    float pbest = -CUDART_INF_F; int pidx = 0;
    float tbest = -CUDART_INF_F; int tidx = 0;
    #pragma unroll
    for (int k = 0; k < 8; k++) {
        const int base = idx[k];
        if (a[k].x > pbest) { pbest = a[k].x; pidx = base + 0; }
        if (a[k].y > pbest) { pbest = a[k].y; pidx = base + 1; }
        if (a[k].z > pbest) { pbest = a[k].z; pidx = base + 2; }
        if (a[k].w > pbest) { pbest = a[k].w; pidx = base + 3; }
        if (b[k].x > tbest) { tbest = b[k].x; tidx = base + 0; }
        if (b[k].y > tbest) { tbest = b[k].y; tidx = base + 1; }
        if (b[k].z > tbest) { tbest = b[k].z; tidx = base + 2; }
        if (b[k].w > tbest) { tbest = b[k].w; tidx = base + 3; }
    }

    // Hardware warp argmax: REDUX max of the ordered key, then REDUX min of
    // the index among lanes holding the max (first-occurrence tie-break).
    const unsigned int pkey = f32_ordered_key(pbest);
    const unsigned int tkey = f32_ordered_key(tbest);
    const unsigned int pmax = __reduce_max_sync(0xFFFFFFFFu, pkey);
    const unsigned int tmax = __reduce_max_sync(0xFFFFFFFFu, tkey);
    const unsigned int pw = __reduce_min_sync(
        0xFFFFFFFFu, (pkey == pmax) ? (unsigned int)pidx : 0x7FFFFFFFu);
    const unsigned int tw = __reduce_min_sync(
        0xFFFFFFFFu, (tkey == tmax) ? (unsigned int)tidx : 0x7FFFFFFFu);

    if (lane == 0) {
        // count += 1; hit += (pred == true) — one L2 atomic.
        const unsigned long long v =
            1ull | ((unsigned long long)(pw == tw) << 32);
        atomicAdd(&g_hist[tw], v);
    }
}

// ---------------------------------------------------------------------------
// Kernel 2 (PDL secondary): 1024 threads, one class per thread, fast
// division. Gates on the primary's completion, computes -mean_recall, then
// resets the histogram for the next graph replay.
// ---------------------------------------------------------------------------
__global__ void __launch_bounds__(1024)
finalize_kernel(float* __restrict__ out) {
    cudaGridDependencySynchronize();

    const int tid = threadIdx.x;

    float rec = 0.0f, prs = 0.0f;
    if (tid < NUM_CLASSES) {
        const unsigned long long v = g_hist[tid];
        const unsigned int cnt  = (unsigned int)v;
        const unsigned int hits = (unsigned int)(v >> 32);
        if (cnt > 0) {
            prs = 1.0f;
            // MUFU rcp + mul; rel-err ~2^-22, far below the 1e-3 tolerance.
            rec = __fdividef((float)hits, (float)cnt);
        }
    }

    // 32-warp reduction: warp shuffle, then one warp over smem.
    __shared__ float s_rec[32];
    __shared__ float s_prs[32];
    #pragma unroll
    for (int off = 16; off > 0; off >>= 1) {
        rec += __shfl_down_sync(0xFFFFFFFFu, rec, off);
        prs += __shfl_down_sync(0xFFFFFFFFu, prs, off);
    }
    const int warp = tid >> 5;
    const int lane = tid & 31;
    if (lane == 0) { s_rec[warp] = rec; s_prs[warp] = prs; }
    __syncthreads();
    if (warp == 0) {
        rec = s_rec[lane];
        prs = s_prs[lane];
        #pragma unroll
        for (int off = 16; off > 0; off >>= 1) {
            rec += __shfl_down_sync(0xFFFFFFFFu, rec, off);
            prs += __shfl_down_sync(0xFFFFFFFFu, prs, off);
        }
        if (lane == 0)
            out[0] = (prs > 0.0f) ? -__fdividef(rec, prs) : 0.0f;
    }

    // Reset for the next replay (reads above are ordered before these writes
    // by the __syncthreads in the reduction path).
    if (tid < NUM_CLASSES) {
        g_hist[tid] = 0ull;
    }
}

// ---------------------------------------------------------------------------
extern "C" void kernel_launch(void* const* d_in, const int* in_sizes, int n_in,
                              void* d_out, int out_size) {
    const float4* y_pred = (const float4*)d_in[0];
    const float4* y_true = (const float4*)d_in[1];
    float* out = (float*)d_out;

    argmax_hist_kernel<<<GRID_BLOCKS, MAIN_BLOCK>>>(y_pred, y_true);

    // PDL launch of the finalize kernel: overlap its launch ramp with the
    // primary kernel's execution (R9 best config — no explicit trigger).
    cudaLaunchConfig_t cfg = {};
    cfg.gridDim  = dim3(1, 1, 1);
    cfg.blockDim = dim3(1024, 1, 1);
    cfg.dynamicSmemBytes = 0;
    cudaLaunchAttribute attrs[1];
    attrs[0].id = cudaLaunchAttributeProgrammaticStreamSerialization;
    attrs[0].val.programmaticStreamSerializationAllowed = 1;
    cfg.attrs = attrs;
    cfg.numAttrs = 1;
    cudaLaunchKernelEx(&cfg, finalize_kernel, out);
}